// round 1
// baseline (speedup 1.0000x reference)
#include <cuda_runtime.h>
#include <math.h>

#define NB   8
#define CCH  256
#define HH   128
#define WW   128
#define HWSZ 16384   // HH*WW
#define QKD  64

// ---------------- scratch (device globals; no allocations) ----------------
__device__ float g_Q[(size_t)NB * QKD * HWSZ];   // 32 MB
__device__ float g_K[(size_t)NB * QKD * HWSZ];   // 32 MB
__device__ float g_V[(size_t)NB * CCH * HWSZ];   // 128 MB
__device__ float g_avg[NB * CCH];
__device__ float g_mx [NB * CCH];
__device__ float g_gate[NB * CCH];

// ---------------------------------------------------------------------------
// Projection GEMM: C[M, HWSZ] = Wt[M, 256] @ x_n[256, HWSZ]   (per n = blockIdx.z)
// sel: 0 -> g_Q, 1 -> g_K, 2 -> g_V
// Block tile 64x64, BK=16, 256 threads, 4x4 per-thread tile.
// ---------------------------------------------------------------------------
__global__ void proj_gemm(const float* __restrict__ Wt,
                          const float* __restrict__ x,
                          int sel, int M)
{
    __shared__ float As[16][68];   // [k][m], padded
    __shared__ float Bs[16][64];   // [k][j]

    float* outp = (sel == 0) ? g_Q : (sel == 1) ? g_K : g_V;

    int n  = blockIdx.z;
    const float* B  = x    + (size_t)n * CCH * HWSZ;
    float*       Cp = outp + (size_t)n * M   * HWSZ;

    int m0 = blockIdx.y * 64;
    int p0 = blockIdx.x * 64;
    int t  = threadIdx.x;
    int tx = t & 15, ty = t >> 4;

    float acc[4][4];
#pragma unroll
    for (int a = 0; a < 4; a++)
#pragma unroll
        for (int b = 0; b < 4; b++) acc[a][b] = 0.f;

    for (int kk = 0; kk < CCH; kk += 16) {
        // stage A tile (64 m x 16 k), transposed into As[k][m]
        {
            int m  = t >> 2;
            int k4 = (t & 3) << 2;
            float4 av = *(const float4*)&Wt[(size_t)(m0 + m) * CCH + kk + k4];
            As[k4 + 0][m] = av.x;
            As[k4 + 1][m] = av.y;
            As[k4 + 2][m] = av.z;
            As[k4 + 3][m] = av.w;
        }
        // stage B tile (16 k x 64 j)
        {
            int kc = t >> 4;
            int j4 = (t & 15) << 2;
            *(float4*)&Bs[kc][j4] =
                *(const float4*)&B[(size_t)(kk + kc) * HWSZ + p0 + j4];
        }
        __syncthreads();

#pragma unroll
        for (int kc = 0; kc < 16; kc++) {
            float4 a = *(const float4*)&As[kc][ty << 2];
            float4 b = *(const float4*)&Bs[kc][tx << 2];
            acc[0][0] += a.x * b.x; acc[0][1] += a.x * b.y; acc[0][2] += a.x * b.z; acc[0][3] += a.x * b.w;
            acc[1][0] += a.y * b.x; acc[1][1] += a.y * b.y; acc[1][2] += a.y * b.z; acc[1][3] += a.y * b.w;
            acc[2][0] += a.z * b.x; acc[2][1] += a.z * b.y; acc[2][2] += a.z * b.z; acc[2][3] += a.z * b.w;
            acc[3][0] += a.w * b.x; acc[3][1] += a.w * b.y; acc[3][2] += a.w * b.z; acc[3][3] += a.w * b.w;
        }
        __syncthreads();
    }

#pragma unroll
    for (int r = 0; r < 4; r++) {
        float4 v = make_float4(acc[r][0], acc[r][1], acc[r][2], acc[r][3]);
        *(float4*)&Cp[(size_t)(m0 + (ty << 2) + r) * HWSZ + p0 + (tx << 2)] = v;
    }
}

// ---------------------------------------------------------------------------
// Per-(n,h) row attention. Block = 256 threads, one block per (n,h).
// smem: q[64][128] + k[64][128] + attT[128][132] + v[64][128]  = 165,888 B
// attT stored transposed: attT[j][i] = att[i][j]; softmax over j (rows).
// out (pre-gate) written straight into d_out.
// ---------------------------------------------------------------------------
#define ATT_PITCH 132
__global__ void attn_row(float* __restrict__ out)
{
    extern __shared__ float smem[];
    float* q_s = smem;                        // 8192
    float* k_s = q_s + QKD * WW;              // 8192
    float* at  = k_s + QKD * WW;              // 128*132 = 16896
    float* v_s = at  + WW * ATT_PITCH;        // 8192

    int nh = blockIdx.x;
    int n  = nh >> 7;
    int h  = nh & 127;
    int t  = threadIdx.x;

    const float* Qg = g_Q + (size_t)n * QKD * HWSZ + (size_t)h * WW;
    const float* Kg = g_K + (size_t)n * QKD * HWSZ + (size_t)h * WW;

    // load q,k rows (coalesced float4)
    for (int e = t; e < (QKD * WW) / 4; e += 256) {
        int d  = e >> 5;
        int i4 = (e & 31) << 2;
        *(float4*)&q_s[d * WW + i4] = *(const float4*)&Qg[(size_t)d * HWSZ + i4];
        *(float4*)&k_s[d * WW + i4] = *(const float4*)&Kg[(size_t)d * HWSZ + i4];
    }
    __syncthreads();

    int tx = t & 15, ty = t >> 4;
    int i0 = tx << 3;            // 8 i per thread
    int j0 = ty << 3;            // 8 j per thread

    // ---- logits: attT[j][i] = sum_d k[d][j] * q[d][i] ----
    {
        float acc[8][8];
#pragma unroll
        for (int a = 0; a < 8; a++)
#pragma unroll
            for (int b = 0; b < 8; b++) acc[a][b] = 0.f;

#pragma unroll 4
        for (int d = 0; d < QKD; d++) {
            float4 qa = *(const float4*)&q_s[d * WW + i0];
            float4 qb = *(const float4*)&q_s[d * WW + i0 + 4];
            float4 ka = *(const float4*)&k_s[d * WW + j0];
            float4 kb = *(const float4*)&k_s[d * WW + j0 + 4];
            float qv[8] = {qa.x, qa.y, qa.z, qa.w, qb.x, qb.y, qb.z, qb.w};
            float kv[8] = {ka.x, ka.y, ka.z, ka.w, kb.x, kb.y, kb.z, kb.w};
#pragma unroll
            for (int ju = 0; ju < 8; ju++)
#pragma unroll
                for (int iu = 0; iu < 8; iu++)
                    acc[ju][iu] += kv[ju] * qv[iu];
        }
#pragma unroll
        for (int ju = 0; ju < 8; ju++) {
            *(float4*)&at[(j0 + ju) * ATT_PITCH + i0] =
                make_float4(acc[ju][0], acc[ju][1], acc[ju][2], acc[ju][3]);
            *(float4*)&at[(j0 + ju) * ATT_PITCH + i0 + 4] =
                make_float4(acc[ju][4], acc[ju][5], acc[ju][6], acc[ju][7]);
        }
    }
    __syncthreads();

    // ---- softmax over j for each column i (threads 0..127) ----
    if (t < WW) {
        int i = t;
        float m = -1e30f;
        for (int j = 0; j < WW; j++) m = fmaxf(m, at[j * ATT_PITCH + i]);
        float s = 0.f;
        for (int j = 0; j < WW; j++) {
            float e = __expf(at[j * ATT_PITCH + i] - m);
            at[j * ATT_PITCH + i] = e;
            s += e;
        }
        float inv = 1.f / s;
        for (int j = 0; j < WW; j++) at[j * ATT_PITCH + i] *= inv;
    }

    // ---- out[c][i] = sum_j attT[j][i] * v[c][j], 4 chunks of 64 channels ----
    for (int cc = 0; cc < 4; cc++) {
        __syncthreads();
        const float* Vg = g_V + ((size_t)n * CCH + cc * 64) * HWSZ + (size_t)h * WW;
        for (int e = t; e < (64 * WW) / 4; e += 256) {
            int c  = e >> 5;
            int i4 = (e & 31) << 2;
            *(float4*)&v_s[c * WW + i4] = *(const float4*)&Vg[(size_t)c * HWSZ + i4];
        }
        __syncthreads();

        int c0 = ty << 2;   // 4 channels per thread
        float acc2[4][8];
#pragma unroll
        for (int a = 0; a < 4; a++)
#pragma unroll
            for (int b = 0; b < 8; b++) acc2[a][b] = 0.f;

#pragma unroll 2
        for (int j = 0; j < WW; j++) {
            float4 a0 = *(const float4*)&at[j * ATT_PITCH + i0];
            float4 a1 = *(const float4*)&at[j * ATT_PITCH + i0 + 4];
            float av[8] = {a0.x, a0.y, a0.z, a0.w, a1.x, a1.y, a1.z, a1.w};
#pragma unroll
            for (int w = 0; w < 4; w++) {
                float vv = v_s[(c0 + w) * WW + j];
#pragma unroll
                for (int u = 0; u < 8; u++) acc2[w][u] += vv * av[u];
            }
        }

#pragma unroll
        for (int w = 0; w < 4; w++) {
            size_t base = (((size_t)n * CCH + cc * 64 + c0 + w) * HH + h) * (size_t)WW + i0;
            *(float4*)&out[base]     = make_float4(acc2[w][0], acc2[w][1], acc2[w][2], acc2[w][3]);
            *(float4*)&out[base + 4] = make_float4(acc2[w][4], acc2[w][5], acc2[w][6], acc2[w][7]);
        }
    }
}

// ---------------------------------------------------------------------------
// Per-(n,c) mean & max over HW of pre-gate out
// ---------------------------------------------------------------------------
__global__ void reduce_nc(const float* __restrict__ o)
{
    __shared__ float ss[256], sm2[256];
    int nc = blockIdx.x;
    const float* p = o + (size_t)nc * HWSZ;
    int t = threadIdx.x;

    float s = 0.f, m = -1e30f;
    for (int e = t * 4; e < HWSZ; e += 1024) {
        float4 v = *(const float4*)&p[e];
        s += v.x + v.y + v.z + v.w;
        m = fmaxf(m, fmaxf(fmaxf(v.x, v.y), fmaxf(v.z, v.w)));
    }
    ss[t] = s; sm2[t] = m;
    __syncthreads();
    for (int k = 128; k > 0; k >>= 1) {
        if (t < k) { ss[t] += ss[t + k]; sm2[t] = fmaxf(sm2[t], sm2[t + k]); }
        __syncthreads();
    }
    if (t == 0) { g_avg[nc] = ss[0] * (1.f / HWSZ); g_mx[nc] = sm2[0]; }
}

// ---------------------------------------------------------------------------
// SE gate: gate[n][c] = sigmoid( W2 @ (relu(W1@avg) + relu(W1@mx)) )
// one block, 256 threads
// ---------------------------------------------------------------------------
__global__ void gate_k(const float* __restrict__ W1, const float* __restrict__ W2)
{
    __shared__ float h1[NB][2][16];
    int t = threadIdx.x;

    {   // 8 n * 2 paths * 16 rows = 256 dot products of length 256
        int n    = t >> 5;
        int rem  = t & 31;
        int path = rem >> 4;
        int r    = rem & 15;
        const float* z = (path == 0 ? g_avg : g_mx) + n * CCH;
        float s = 0.f;
        for (int c = 0; c < CCH; c++) s += W1[r * CCH + c] * z[c];
        h1[n][path][r] = fmaxf(s, 0.f);
    }
    __syncthreads();

    int c = t;
    for (int n = 0; n < NB; n++) {
        float g = 0.f;
        for (int r = 0; r < 16; r++)
            g += W2[c * 16 + r] * (h1[n][0][r] + h1[n][1][r]);
        g_gate[n * CCH + c] = 1.f / (1.f + __expf(-g));
    }
}

// ---------------------------------------------------------------------------
// final: out = gama * gate[n,c] * out + x    (in-place on d_out, float4)
// ---------------------------------------------------------------------------
__global__ void final_k(const float* __restrict__ x,
                        const float* __restrict__ gama,
                        float* __restrict__ o)
{
    size_t idx = (size_t)blockIdx.x * blockDim.x + threadIdx.x;   // float4 index
    float g = gama[0];
    float4 ov = ((const float4*)o)[idx];
    float4 xv = ((const float4*)x)[idx];
    float gt = g * g_gate[idx >> 12];   // 4096 float4 per (n,c)
    float4 r;
    r.x = gt * ov.x + xv.x;
    r.y = gt * ov.y + xv.y;
    r.z = gt * ov.z + xv.z;
    r.w = gt * ov.w + xv.w;
    ((float4*)o)[idx] = r;
}

// ---------------------------------------------------------------------------
extern "C" void kernel_launch(void* const* d_in, const int* in_sizes, int n_in,
                              void* d_out, int out_size)
{
    const float* x    = (const float*)d_in[0];
    const float* Wq   = (const float*)d_in[1];
    const float* Wk   = (const float*)d_in[2];
    const float* Wv   = (const float*)d_in[3];
    const float* W1   = (const float*)d_in[4];
    const float* W2   = (const float*)d_in[5];
    const float* gama = (const float*)d_in[6];
    float* out = (float*)d_out;

    const int ATTN_SMEM = (QKD * WW + QKD * WW + WW * ATT_PITCH + 64 * WW) * 4;
    cudaFuncSetAttribute(attn_row, cudaFuncAttributeMaxDynamicSharedMemorySize, ATTN_SMEM);

    // projections
    proj_gemm<<<dim3(HWSZ / 64, 1, NB), 256>>>(Wq, x, 0, QKD);
    proj_gemm<<<dim3(HWSZ / 64, 1, NB), 256>>>(Wk, x, 1, QKD);
    proj_gemm<<<dim3(HWSZ / 64, 4, NB), 256>>>(Wv, x, 2, CCH);

    // row attention -> pre-gate out in d_out
    attn_row<<<NB * HH, 256, ATTN_SMEM>>>(out);

    // SE gate
    reduce_nc<<<NB * CCH, 256>>>(out);
    gate_k<<<1, 256>>>(W1, W2);

    // final residual
    final_k<<<(NB * CCH * HWSZ) / (4 * 256), 256>>>(x, gama, out);
}

// round 2
// speedup vs baseline: 1.0762x; 1.0762x over previous
#include <cuda_runtime.h>
#include <math.h>

#define NB   8
#define CCH  256
#define HH   128
#define WW   128
#define HWSZ 16384
#define QKD  64

typedef unsigned long long u64;

__device__ __forceinline__ u64 pack2(float lo, float hi) {
    u64 r; asm("mov.b64 %0,{%1,%2};" : "=l"(r) : "f"(lo), "f"(hi)); return r;
}
__device__ __forceinline__ u64 bcast2(float v) { return pack2(v, v); }
__device__ __forceinline__ void ffma2(u64& d, u64 a, u64 b) {
    asm("fma.rn.f32x2 %0, %1, %2, %0;" : "+l"(d) : "l"(a), "l"(b));
}
__device__ __forceinline__ float2 unpack2(u64 v) {
    float2 f; asm("mov.b64 {%0,%1},%2;" : "=f"(f.x), "=f"(f.y) : "l"(v)); return f;
}

// ---------------- scratch ----------------
__device__ float g_Q[(size_t)NB * QKD * HWSZ];
__device__ float g_K[(size_t)NB * QKD * HWSZ];
__device__ float g_V[(size_t)NB * CCH * HWSZ];
__device__ float g_avg[NB * CCH];
__device__ float g_mx [NB * CCH];
__device__ float g_gate[NB * CCH];

// ---------------------------------------------------------------------------
// Fused Q/K projection: rows 0..63 = Wq, 64..127 = Wk. BM=128,BN=128,BK=16.
// 256 threads, 8m x 8n per thread, f32x2 packed along n.
// ---------------------------------------------------------------------------
__global__ void proj_qk(const float* __restrict__ Wq,
                        const float* __restrict__ Wk,
                        const float* __restrict__ x)
{
    __shared__ float As[16][132];
    __shared__ float Bs[16][128];

    int n  = blockIdx.z;
    int p0 = blockIdx.x * 128;
    const float* B = x + (size_t)n * CCH * HWSZ;
    int t  = threadIdx.x;
    int tx = t & 15, ty = t >> 4;

    u64 acc[8][4];
#pragma unroll
    for (int a = 0; a < 8; a++)
#pragma unroll
        for (int b = 0; b < 4; b++) acc[a][b] = 0ull;

    for (int kk = 0; kk < CCH; kk += 16) {
        {   // stage A: m = t>>1 (0..127), k8 = (t&1)*8
            int m  = t >> 1;
            int k8 = (t & 1) << 3;
            const float* wrow = (m < 64) ? &Wq[(size_t)m * CCH]
                                         : &Wk[(size_t)(m - 64) * CCH];
            float4 a0 = *(const float4*)&wrow[kk + k8];
            float4 a1 = *(const float4*)&wrow[kk + k8 + 4];
            As[k8 + 0][m] = a0.x; As[k8 + 1][m] = a0.y;
            As[k8 + 2][m] = a0.z; As[k8 + 3][m] = a0.w;
            As[k8 + 4][m] = a1.x; As[k8 + 5][m] = a1.y;
            As[k8 + 6][m] = a1.z; As[k8 + 7][m] = a1.w;
        }
        {   // stage B: k = t>>4, j8 = (t&15)*8
            int k  = t >> 4;
            int j8 = (t & 15) << 3;
            const float* brow = &B[(size_t)(kk + k) * HWSZ + p0 + j8];
            *(float4*)&Bs[k][j8]     = *(const float4*)&brow[0];
            *(float4*)&Bs[k][j8 + 4] = *(const float4*)&brow[4];
        }
        __syncthreads();

#pragma unroll
        for (int kc = 0; kc < 16; kc++) {
            float a[8];
            *(float4*)&a[0] = *(const float4*)&As[kc][ty << 3];
            *(float4*)&a[4] = *(const float4*)&As[kc][(ty << 3) + 4];
            const u64* bp = (const u64*)&Bs[kc][tx << 3];
            u64 b2[4] = {bp[0], bp[1], bp[2], bp[3]};
#pragma unroll
            for (int mi = 0; mi < 8; mi++) {
                u64 av = bcast2(a[mi]);
#pragma unroll
                for (int p = 0; p < 4; p++) ffma2(acc[mi][p], av, b2[p]);
            }
        }
        __syncthreads();
    }

#pragma unroll
    for (int mi = 0; mi < 8; mi++) {
        int m = (ty << 3) + mi;
        float* Cp = (m < 64) ? &g_Q[((size_t)n * QKD + m) * HWSZ]
                             : &g_K[((size_t)n * QKD + (m - 64)) * HWSZ];
        float2 f0 = unpack2(acc[mi][0]), f1 = unpack2(acc[mi][1]);
        float2 f2 = unpack2(acc[mi][2]), f3 = unpack2(acc[mi][3]);
        *(float4*)&Cp[p0 + (tx << 3)]     = make_float4(f0.x, f0.y, f1.x, f1.y);
        *(float4*)&Cp[p0 + (tx << 3) + 4] = make_float4(f2.x, f2.y, f3.x, f3.y);
    }
}

// ---------------------------------------------------------------------------
// V projection: BM=128 (blockIdx.y), BN=128, BK=16, 256 threads, 8x8, f32x2.
// ---------------------------------------------------------------------------
__global__ void proj_v(const float* __restrict__ Wv,
                       const float* __restrict__ x)
{
    __shared__ float As[16][132];
    __shared__ float Bs[16][128];

    int n  = blockIdx.z;
    int m0 = blockIdx.y * 128;
    int p0 = blockIdx.x * 128;
    const float* B = x + (size_t)n * CCH * HWSZ;
    int t  = threadIdx.x;
    int tx = t & 15, ty = t >> 4;

    u64 acc[8][4];
#pragma unroll
    for (int a = 0; a < 8; a++)
#pragma unroll
        for (int b = 0; b < 4; b++) acc[a][b] = 0ull;

    for (int kk = 0; kk < CCH; kk += 16) {
        {
            int m  = t >> 1;
            int k8 = (t & 1) << 3;
            const float* wrow = &Wv[(size_t)(m0 + m) * CCH];
            float4 a0 = *(const float4*)&wrow[kk + k8];
            float4 a1 = *(const float4*)&wrow[kk + k8 + 4];
            As[k8 + 0][m] = a0.x; As[k8 + 1][m] = a0.y;
            As[k8 + 2][m] = a0.z; As[k8 + 3][m] = a0.w;
            As[k8 + 4][m] = a1.x; As[k8 + 5][m] = a1.y;
            As[k8 + 6][m] = a1.z; As[k8 + 7][m] = a1.w;
        }
        {
            int k  = t >> 4;
            int j8 = (t & 15) << 3;
            const float* brow = &B[(size_t)(kk + k) * HWSZ + p0 + j8];
            *(float4*)&Bs[k][j8]     = *(const float4*)&brow[0];
            *(float4*)&Bs[k][j8 + 4] = *(const float4*)&brow[4];
        }
        __syncthreads();

#pragma unroll
        for (int kc = 0; kc < 16; kc++) {
            float a[8];
            *(float4*)&a[0] = *(const float4*)&As[kc][ty << 3];
            *(float4*)&a[4] = *(const float4*)&As[kc][(ty << 3) + 4];
            const u64* bp = (const u64*)&Bs[kc][tx << 3];
            u64 b2[4] = {bp[0], bp[1], bp[2], bp[3]};
#pragma unroll
            for (int mi = 0; mi < 8; mi++) {
                u64 av = bcast2(a[mi]);
#pragma unroll
                for (int p = 0; p < 4; p++) ffma2(acc[mi][p], av, b2[p]);
            }
        }
        __syncthreads();
    }

#pragma unroll
    for (int mi = 0; mi < 8; mi++) {
        float* Cp = &g_V[((size_t)n * CCH + m0 + (ty << 3) + mi) * HWSZ];
        float2 f0 = unpack2(acc[mi][0]), f1 = unpack2(acc[mi][1]);
        float2 f2 = unpack2(acc[mi][2]), f3 = unpack2(acc[mi][3]);
        *(float4*)&Cp[p0 + (tx << 3)]     = make_float4(f0.x, f0.y, f1.x, f1.y);
        *(float4*)&Cp[p0 + (tx << 3) + 4] = make_float4(f2.x, f2.y, f3.x, f3.y);
    }
}

// ---------------------------------------------------------------------------
// Row attention: one block per (n,h), 256 threads, f32x2.
// smem: q[64*128] k[64*128] at[128*132]; v_s (64*130) overlays q after logits.
// ---------------------------------------------------------------------------
#define ATT_PITCH 132
#define V_PITCH   130
__global__ void attn_row(float* __restrict__ out)
{
    extern __shared__ float smem[];
    float* q_s = smem;                 // 8192 floats
    float* k_s = smem + 8192;          // 8192 floats
    float* at  = smem + 16384;         // 128*132 = 16896 floats
    float* v_s = smem;                 // overlay (64*130 = 8320 floats)

    int nh = blockIdx.x;
    int n  = nh >> 7;
    int h  = nh & 127;
    int t  = threadIdx.x;
    int tx = t & 15, ty = t >> 4;
    int i0 = tx << 3;

    const float* Qg = g_Q + (size_t)n * QKD * HWSZ + (size_t)h * WW;
    const float* Kg = g_K + (size_t)n * QKD * HWSZ + (size_t)h * WW;

    for (int e = t; e < (QKD * WW) / 4; e += 256) {
        int d  = e >> 5;
        int i4 = (e & 31) << 2;
        *(float4*)&q_s[d * WW + i4] = *(const float4*)&Qg[(size_t)d * HWSZ + i4];
        *(float4*)&k_s[d * WW + i4] = *(const float4*)&Kg[(size_t)d * HWSZ + i4];
    }
    __syncthreads();

    // ---- logits: attT[j][i] = sum_d k[d][j]*q[d][i]; 8j x 8i per thread ----
    {
        int j0 = ty << 3;
        u64 acc[8][4];
#pragma unroll
        for (int a = 0; a < 8; a++)
#pragma unroll
            for (int b = 0; b < 4; b++) acc[a][b] = 0ull;

#pragma unroll 4
        for (int d = 0; d < QKD; d++) {
            const u64* qp = (const u64*)&q_s[d * WW + i0];
            u64 q2[4] = {qp[0], qp[1], qp[2], qp[3]};
            float kv[8];
            *(float4*)&kv[0] = *(const float4*)&k_s[d * WW + j0];
            *(float4*)&kv[4] = *(const float4*)&k_s[d * WW + j0 + 4];
#pragma unroll
            for (int ju = 0; ju < 8; ju++) {
                u64 kb = bcast2(kv[ju]);
#pragma unroll
                for (int p = 0; p < 4; p++) ffma2(acc[ju][p], kb, q2[p]);
            }
        }
#pragma unroll
        for (int ju = 0; ju < 8; ju++) {
            u64* ap = (u64*)&at[(j0 + ju) * ATT_PITCH + i0];
#pragma unroll
            for (int p = 0; p < 4; p++) ap[p] = acc[ju][p];
        }
    }
    __syncthreads();

    // ---- softmax over j per column i ----
    if (t < WW) {
        int i = t;
        float m = -1e30f;
        for (int j = 0; j < WW; j++) m = fmaxf(m, at[j * ATT_PITCH + i]);
        float s = 0.f;
        for (int j = 0; j < WW; j++) {
            float e = __expf(at[j * ATT_PITCH + i] - m);
            at[j * ATT_PITCH + i] = e;
            s += e;
        }
        float inv = 1.f / s;
        for (int j = 0; j < WW; j++) at[j * ATT_PITCH + i] *= inv;
    }

    // ---- out[c][i] = sum_j attT[j][i]*v[c][j]; 4 chunks of 64 channels ----
    int c0 = ty << 2;
    for (int cc = 0; cc < 4; cc++) {
        __syncthreads();   // softmax done / previous chunk compute done
        const float* Vg = g_V + ((size_t)n * CCH + cc * 64) * HWSZ + (size_t)h * WW;
        for (int e = t; e < (64 * WW) / 4; e += 256) {
            int c  = e >> 5;
            int i4 = (e & 31) << 2;
            float4 v4 = *(const float4*)&Vg[(size_t)c * HWSZ + i4];
            float* vd = &v_s[c * V_PITCH + i4];
            vd[0] = v4.x; vd[1] = v4.y; vd[2] = v4.z; vd[3] = v4.w;
        }
        __syncthreads();

        u64 acc2[4][4];
#pragma unroll
        for (int a = 0; a < 4; a++)
#pragma unroll
            for (int b = 0; b < 4; b++) acc2[a][b] = 0ull;

#pragma unroll 2
        for (int j = 0; j < WW; j++) {
            const u64* ap = (const u64*)&at[j * ATT_PITCH + i0];
            u64 a2[4] = {ap[0], ap[1], ap[2], ap[3]};
#pragma unroll
            for (int w = 0; w < 4; w++) {
                u64 vb = bcast2(v_s[(c0 + w) * V_PITCH + j]);
#pragma unroll
                for (int p = 0; p < 4; p++) ffma2(acc2[w][p], vb, a2[p]);
            }
        }

#pragma unroll
        for (int w = 0; w < 4; w++) {
            size_t base = (((size_t)n * CCH + cc * 64 + c0 + w) * HH + h) * (size_t)WW + i0;
            float2 f0 = unpack2(acc2[w][0]), f1 = unpack2(acc2[w][1]);
            float2 f2 = unpack2(acc2[w][2]), f3 = unpack2(acc2[w][3]);
            *(float4*)&out[base]     = make_float4(f0.x, f0.y, f1.x, f1.y);
            *(float4*)&out[base + 4] = make_float4(f2.x, f2.y, f3.x, f3.y);
        }
    }
}

// ---------------------------------------------------------------------------
__global__ void reduce_nc(const float* __restrict__ o)
{
    __shared__ float ss[256], sm2[256];
    int nc = blockIdx.x;
    const float* p = o + (size_t)nc * HWSZ;
    int t = threadIdx.x;

    float s = 0.f, m = -1e30f;
    for (int e = t * 4; e < HWSZ; e += 1024) {
        float4 v = *(const float4*)&p[e];
        s += v.x + v.y + v.z + v.w;
        m = fmaxf(m, fmaxf(fmaxf(v.x, v.y), fmaxf(v.z, v.w)));
    }
    ss[t] = s; sm2[t] = m;
    __syncthreads();
    for (int k = 128; k > 0; k >>= 1) {
        if (t < k) { ss[t] += ss[t + k]; sm2[t] = fmaxf(sm2[t], sm2[t + k]); }
        __syncthreads();
    }
    if (t == 0) { g_avg[nc] = ss[0] * (1.f / HWSZ); g_mx[nc] = sm2[0]; }
}

__global__ void gate_k(const float* __restrict__ W1, const float* __restrict__ W2)
{
    __shared__ float h1[NB][2][16];
    int t = threadIdx.x;
    {
        int n    = t >> 5;
        int rem  = t & 31;
        int path = rem >> 4;
        int r    = rem & 15;
        const float* z = (path == 0 ? g_avg : g_mx) + n * CCH;
        float s = 0.f;
        for (int c = 0; c < CCH; c++) s += W1[r * CCH + c] * z[c];
        h1[n][path][r] = fmaxf(s, 0.f);
    }
    __syncthreads();
    int c = t;
    for (int n = 0; n < NB; n++) {
        float g = 0.f;
        for (int r = 0; r < 16; r++)
            g += W2[c * 16 + r] * (h1[n][0][r] + h1[n][1][r]);
        g_gate[n * CCH + c] = 1.f / (1.f + __expf(-g));
    }
}

__global__ void final_k(const float* __restrict__ x,
                        const float* __restrict__ gama,
                        float* __restrict__ o)
{
    size_t idx = (size_t)blockIdx.x * blockDim.x + threadIdx.x;
    float g = gama[0];
    float4 ov = ((const float4*)o)[idx];
    float4 xv = ((const float4*)x)[idx];
    float gt = g * g_gate[idx >> 12];
    float4 r;
    r.x = gt * ov.x + xv.x;
    r.y = gt * ov.y + xv.y;
    r.z = gt * ov.z + xv.z;
    r.w = gt * ov.w + xv.w;
    ((float4*)o)[idx] = r;
}

// ---------------------------------------------------------------------------
extern "C" void kernel_launch(void* const* d_in, const int* in_sizes, int n_in,
                              void* d_out, int out_size)
{
    const float* x    = (const float*)d_in[0];
    const float* Wq   = (const float*)d_in[1];
    const float* Wk   = (const float*)d_in[2];
    const float* Wv   = (const float*)d_in[3];
    const float* W1   = (const float*)d_in[4];
    const float* W2   = (const float*)d_in[5];
    const float* gama = (const float*)d_in[6];
    float* out = (float*)d_out;

    const int ATTN_SMEM = (16384 + WW * ATT_PITCH) * 4;   // 133,120 B
    cudaFuncSetAttribute(attn_row, cudaFuncAttributeMaxDynamicSharedMemorySize, ATTN_SMEM);

    proj_qk<<<dim3(HWSZ / 128, 1, NB), 256>>>(Wq, Wk, x);
    proj_v <<<dim3(HWSZ / 128, 2, NB), 256>>>(Wv, x);

    attn_row<<<NB * HH, 256, ATTN_SMEM>>>(out);

    reduce_nc<<<NB * CCH, 256>>>(out);
    gate_k<<<1, 256>>>(W1, W2);

    final_k<<<(NB * CCH * HWSZ) / (4 * 256), 256>>>(x, gama, out);
}

// round 3
// speedup vs baseline: 3.6040x; 3.3487x over previous
#include <cuda_runtime.h>
#include <cuda_bf16.h>
#include <math.h>

#define NB   8
#define CCH  256
#define HH   128
#define WW   128
#define HWSZ 16384
#define QKD  64

typedef unsigned int u32;
typedef __nv_bfloat16 bf16;

// ---------------- scratch (16B-aligned for vector access) ----------------
__device__ __align__(16) bf16 g_xb[(size_t)NB * CCH * HWSZ];
__device__ __align__(16) bf16 g_Wb[384 * CCH];
__device__ __align__(16) bf16 g_Qb[(size_t)NB * QKD * HWSZ];
__device__ __align__(16) bf16 g_Kb[(size_t)NB * QKD * HWSZ];
__device__ __align__(16) bf16 g_Vb[(size_t)NB * CCH * HWSZ];
__device__ float g_avg[NB * CCH];
__device__ float g_mx [NB * CCH];
__device__ float g_gate[NB * CCH];

// ---------------- helpers ----------------
__device__ __forceinline__ u32 smem_u32(const void* p) {
    u32 a;
    asm("{.reg .u64 t; cvta.to.shared.u64 t, %1; cvt.u32.u64 %0, t;}"
        : "=r"(a) : "l"(p));
    return a;
}
__device__ __forceinline__ void ldsm4(u32* r, u32 a) {
    asm volatile("ldmatrix.sync.aligned.m8n8.x4.shared.b16 {%0,%1,%2,%3},[%4];"
        : "=r"(r[0]), "=r"(r[1]), "=r"(r[2]), "=r"(r[3]) : "r"(a));
}
__device__ __forceinline__ void ldsm4t(u32* r, u32 a) {
    asm volatile("ldmatrix.sync.aligned.m8n8.x4.trans.shared.b16 {%0,%1,%2,%3},[%4];"
        : "=r"(r[0]), "=r"(r[1]), "=r"(r[2]), "=r"(r[3]) : "r"(a));
}
__device__ __forceinline__ void mma_bf(float* d, const u32* a, const u32* b) {
    asm volatile(
        "mma.sync.aligned.m16n8k16.row.col.f32.bf16.bf16.f32 "
        "{%0,%1,%2,%3},{%4,%5,%6,%7},{%8,%9},{%0,%1,%2,%3};"
        : "+f"(d[0]), "+f"(d[1]), "+f"(d[2]), "+f"(d[3])
        : "r"(a[0]), "r"(a[1]), "r"(a[2]), "r"(a[3]), "r"(b[0]), "r"(b[1]));
}
__device__ __forceinline__ u32 packbf(float lo, float hi) {
    u32 r; asm("cvt.rn.bf16x2.f32 %0,%1,%2;" : "=r"(r) : "f"(hi), "f"(lo));
    return r;
}

// ---------------------------------------------------------------------------
// conversions
// ---------------------------------------------------------------------------
__global__ void convert_x(const float* __restrict__ x)
{
    size_t i4 = (size_t)blockIdx.x * 256 + threadIdx.x;
    float4 v = ((const float4*)x)[i4];
    uint2 o;
    o.x = packbf(v.x, v.y);
    o.y = packbf(v.z, v.w);
    ((uint2*)g_xb)[i4] = o;
}

__global__ void convert_w(const float* __restrict__ Wq,
                          const float* __restrict__ Wk,
                          const float* __restrict__ Wv)
{
    int i = blockIdx.x * 256 + threadIdx.x;   // 0 .. 384*256-1
    float v;
    if (i < 64 * 256)       v = Wq[i];
    else if (i < 128 * 256) v = Wk[i - 64 * 256];
    else                    v = Wv[i - 128 * 256];
    g_Wb[i] = __float2bfloat16(v);
}

// ---------------------------------------------------------------------------
// Fused QKV projection GEMM (bf16 tensor cores).
// C[384,16384] = W[384,256] @ xb[256,16384] per batch.
// grid = (128 n-blocks, 3 m-blocks, 8 batch); block = 256 (8 warps, 2x4).
// by==0 -> rows 0..127 = Q(0-63)+K(64-127); by 1,2 -> V rows.
// ---------------------------------------------------------------------------
#define PA 40
#define PB 136
#define PC 136
__global__ __launch_bounds__(256) void proj_mma()
{
    extern __shared__ bf16 sm[];
    bf16* A_s = sm;                       // 128 x 40
    bf16* B_s = sm + 128 * PA;            // 32  x 136
    bf16* C_s = sm + 128 * PA + 32 * PB;  // 128 x 136

    int t = threadIdx.x, l = t & 31, w = t >> 5;
    int bz = blockIdx.z, by = blockIdx.y;
    int p0 = blockIdx.x * 128;
    int m0 = (w & 1) * 64, n0 = (w >> 1) * 32;

    const bf16* Wp = g_Wb + (size_t)(by * 128) * CCH;
    const bf16* Xp = g_xb + (size_t)bz * CCH * HWSZ + p0;

    float acc[4][4][4];
#pragma unroll
    for (int a = 0; a < 4; a++)
#pragma unroll
        for (int b = 0; b < 4; b++)
#pragma unroll
            for (int c = 0; c < 4; c++) acc[a][b][c] = 0.f;

    for (int kk = 0; kk < CCH; kk += 32) {
        {   // A tile: 128 rows x 32 cols
            int r = t >> 1, c = (t & 1) * 16;
            *(uint4*)(A_s + r * PA + c)     = *(const uint4*)(Wp + (size_t)r * CCH + kk + c);
            *(uint4*)(A_s + r * PA + c + 8) = *(const uint4*)(Wp + (size_t)r * CCH + kk + c + 8);
        }
        {   // B tile: 32 rows x 128 cols
            int r = t >> 3, c = (t & 7) * 8;
            *(uint4*)(B_s + r * PB + c)      = *(const uint4*)(Xp + (size_t)(kk + r) * HWSZ + c);
            *(uint4*)(B_s + r * PB + c + 64) = *(const uint4*)(Xp + (size_t)(kk + r) * HWSZ + c + 64);
        }
        __syncthreads();

#pragma unroll
        for (int ks = 0; ks < 2; ks++) {
            int k0 = ks * 16;
            u32 a[4][4], b[4][2];
            int ar  = ((l >> 3) & 1) * 8 + (l & 7);
            int acl = k0 + (l >> 4) * 8;
#pragma unroll
            for (int mf = 0; mf < 4; mf++)
                ldsm4(a[mf], smem_u32(A_s + (m0 + mf * 16 + ar) * PA + acl));
            int br  = k0 + ((l >> 3) & 1) * 8 + (l & 7);
            int bcl = (l >> 4) * 8;
#pragma unroll
            for (int bi = 0; bi < 2; bi++) {
                u32 r4[4];
                ldsm4t(r4, smem_u32(B_s + br * PB + n0 + bi * 16 + bcl));
                b[bi * 2][0] = r4[0]; b[bi * 2][1] = r4[1];
                b[bi * 2 + 1][0] = r4[2]; b[bi * 2 + 1][1] = r4[3];
            }
#pragma unroll
            for (int mf = 0; mf < 4; mf++)
#pragma unroll
                for (int nf = 0; nf < 4; nf++)
                    mma_bf(acc[mf][nf], a[mf], b[nf]);
        }
        __syncthreads();
    }

    // epilogue: frags -> C_s (bf16) -> coalesced gmem
    int g = l >> 2, tq = l & 3;
#pragma unroll
    for (int mf = 0; mf < 4; mf++)
#pragma unroll
        for (int nf = 0; nf < 4; nf++) {
            int col = n0 + nf * 8 + tq * 2;
            *(u32*)(C_s + (m0 + mf * 16 + g) * PC + col)     = packbf(acc[mf][nf][0], acc[mf][nf][1]);
            *(u32*)(C_s + (m0 + mf * 16 + g + 8) * PC + col) = packbf(acc[mf][nf][2], acc[mf][nf][3]);
        }
    __syncthreads();

    for (int e = t; e < 128 * 16; e += 256) {
        int r = e >> 4, c = (e & 15) * 8;
        bf16* dst;
        if (by == 0)
            dst = (r < 64) ? g_Qb + ((size_t)bz * QKD + r) * HWSZ
                           : g_Kb + ((size_t)bz * QKD + r - 64) * HWSZ;
        else
            dst = g_Vb + ((size_t)bz * CCH + (by - 1) * 128 + r) * HWSZ;
        *(uint4*)(dst + p0 + c) = *(const uint4*)(C_s + r * PC + c);
    }
}

// ---------------------------------------------------------------------------
// Row attention, tensor cores. One block per (n,h), 256 threads (8 warps).
// Phase 1: S[i][j] = sum_d q[i,d]k[j,d]  (A,B via ldmatrix.trans from [d][x])
// Phase 2: softmax over j (fp32), exp stored bf16 in att_s, 1/sum in inv_s.
// Phase 3: out[c][i] = (sum_j v[c][j]*exp[i][j]) * inv[i], 2 chunks of 128 c.
// ---------------------------------------------------------------------------
#define QP 136
#define SP 134
__global__ __launch_bounds__(256, 2) void attn_mma(float* __restrict__ out)
{
    extern __shared__ char smc[];
    bf16*  q_s   = (bf16*)smc;                   // 64x136
    bf16*  k_s   = q_s + 64 * QP;                // 64x136
    float* S_s   = (float*)(smc + 34816);        // 128x134 fp32
    float* inv_s = (float*)(smc + 103424);       // 128 fp32
    bf16*  att_s = (bf16*)smc;                   // overlay q/k: 128x136
    bf16*  v_s   = (bf16*)(smc + 34816);         // overlay S : 128x136

    int nh = blockIdx.x, n = nh >> 7, h = nh & 127;
    int t = threadIdx.x, l = t & 31, w = t >> 5;
    int m0 = (w & 1) * 64, n0 = (w >> 1) * 32;

    const bf16* Qg = g_Qb + (size_t)n * QKD * HWSZ + h * WW;
    const bf16* Kg = g_Kb + (size_t)n * QKD * HWSZ + h * WW;

    for (int e = t; e < 1024; e += 256) {
        int d = e >> 4, c = (e & 15) * 8;
        *(uint4*)(q_s + d * QP + c) = *(const uint4*)(Qg + (size_t)d * HWSZ + c);
        *(uint4*)(k_s + d * QP + c) = *(const uint4*)(Kg + (size_t)d * HWSZ + c);
    }
    __syncthreads();

    // ---- logits ----
    {
        float acc[4][4][4];
#pragma unroll
        for (int a = 0; a < 4; a++)
#pragma unroll
            for (int b = 0; b < 4; b++)
#pragma unroll
                for (int c = 0; c < 4; c++) acc[a][b][c] = 0.f;

#pragma unroll
        for (int ks = 0; ks < 4; ks++) {
            int k0 = ks * 16;
            u32 a[4][4], b[4][2];
            int ar  = k0 + ((l >> 4) << 3) + (l & 7);    // d row
            int acl = ((l >> 3) & 1) * 8;                // i col offset
#pragma unroll
            for (int mf = 0; mf < 4; mf++)
                ldsm4t(a[mf], smem_u32(q_s + ar * QP + m0 + mf * 16 + acl));
            int br  = k0 + ((l >> 3) & 1) * 8 + (l & 7);
            int bcl = (l >> 4) * 8;
#pragma unroll
            for (int bi = 0; bi < 2; bi++) {
                u32 r4[4];
                ldsm4t(r4, smem_u32(k_s + br * QP + n0 + bi * 16 + bcl));
                b[bi * 2][0] = r4[0]; b[bi * 2][1] = r4[1];
                b[bi * 2 + 1][0] = r4[2]; b[bi * 2 + 1][1] = r4[3];
            }
#pragma unroll
            for (int mf = 0; mf < 4; mf++)
#pragma unroll
                for (int nf = 0; nf < 4; nf++)
                    mma_bf(acc[mf][nf], a[mf], b[nf]);
        }
        int g = l >> 2, tq = l & 3;
#pragma unroll
        for (int mf = 0; mf < 4; mf++)
#pragma unroll
            for (int nf = 0; nf < 4; nf++) {
                int i = m0 + mf * 16 + g, j = n0 + nf * 8 + tq * 2;
                *(float2*)(S_s + i * SP + j)       = make_float2(acc[mf][nf][0], acc[mf][nf][1]);
                *(float2*)(S_s + (i + 8) * SP + j) = make_float2(acc[mf][nf][2], acc[mf][nf][3]);
            }
    }
    __syncthreads();

    // ---- softmax (rows i, interleaved halves per thread pair) ----
    {
        int i = t >> 1, hf = t & 1;
        const float* Sr = S_s + i * SP;
        float m = -1e30f;
#pragma unroll 8
        for (int jj = 0; jj < 64; jj++) m = fmaxf(m, Sr[2 * jj + hf]);
        m = fmaxf(m, __shfl_xor_sync(0xffffffffu, m, 1));
        float s = 0.f;
        bf16* ar = att_s + i * QP;
#pragma unroll 8
        for (int jj = 0; jj < 64; jj++) {
            int j = 2 * jj + hf;
            float e = __expf(Sr[j] - m);
            s += e;
            ar[j] = __float2bfloat16(e);
        }
        s += __shfl_xor_sync(0xffffffffu, s, 1);
        if (hf == 0) inv_s[i] = 1.f / s;
    }

    // ---- att . V : M = c (chunked 128), N = i, K = j ----
    for (int cc = 0; cc < 2; cc++) {
        __syncthreads();
        const bf16* Vg = g_Vb + ((size_t)n * CCH + cc * 128) * HWSZ + h * WW;
        for (int e = t; e < 2048; e += 256) {
            int c = e >> 4, col = (e & 15) * 8;
            *(uint4*)(v_s + c * QP + col) = *(const uint4*)(Vg + (size_t)c * HWSZ + col);
        }
        __syncthreads();

        float acc[4][4][4];
#pragma unroll
        for (int a = 0; a < 4; a++)
#pragma unroll
            for (int b = 0; b < 4; b++)
#pragma unroll
                for (int c = 0; c < 4; c++) acc[a][b][c] = 0.f;

#pragma unroll
        for (int ks = 0; ks < 8; ks++) {
            int k0 = ks * 16;
            u32 a[4][4], b[4][2];
            int ar  = ((l >> 3) & 1) * 8 + (l & 7);
            int acl = k0 + (l >> 4) * 8;
#pragma unroll
            for (int mf = 0; mf < 4; mf++)
                ldsm4(a[mf], smem_u32(v_s + (m0 + mf * 16 + ar) * QP + acl));
            int brr = (l >> 4) * 8 + (l & 7);            // i row within n16
            int bcl = k0 + ((l >> 3) & 1) * 8;           // j col
#pragma unroll
            for (int bi = 0; bi < 2; bi++) {
                u32 r4[4];
                ldsm4(r4, smem_u32(att_s + (n0 + bi * 16 + brr) * QP + bcl));
                b[bi * 2][0] = r4[0]; b[bi * 2][1] = r4[1];
                b[bi * 2 + 1][0] = r4[2]; b[bi * 2 + 1][1] = r4[3];
            }
#pragma unroll
            for (int mf = 0; mf < 4; mf++)
#pragma unroll
                for (int nf = 0; nf < 4; nf++)
                    mma_bf(acc[mf][nf], a[mf], b[nf]);
        }

        int g = l >> 2, tq = l & 3;
#pragma unroll
        for (int mf = 0; mf < 4; mf++)
#pragma unroll
            for (int nf = 0; nf < 4; nf++) {
                int c = m0 + mf * 16 + g;
                int i = n0 + nf * 8 + tq * 2;
                float2 iv = *(float2*)(inv_s + i);
                size_t b0 = (((size_t)n * CCH + cc * 128 + c) * HH + h) * (size_t)WW + i;
                size_t b1 = (((size_t)n * CCH + cc * 128 + c + 8) * HH + h) * (size_t)WW + i;
                *(float2*)(out + b0) = make_float2(acc[mf][nf][0] * iv.x, acc[mf][nf][1] * iv.y);
                *(float2*)(out + b1) = make_float2(acc[mf][nf][2] * iv.x, acc[mf][nf][3] * iv.y);
            }
    }
}

// ---------------------------------------------------------------------------
__global__ void reduce_nc(const float* __restrict__ o)
{
    __shared__ float ss[256], sm2[256];
    int nc = blockIdx.x;
    const float* p = o + (size_t)nc * HWSZ;
    int t = threadIdx.x;

    float s = 0.f, m = -1e30f;
    for (int e = t * 4; e < HWSZ; e += 1024) {
        float4 v = *(const float4*)&p[e];
        s += v.x + v.y + v.z + v.w;
        m = fmaxf(m, fmaxf(fmaxf(v.x, v.y), fmaxf(v.z, v.w)));
    }
    ss[t] = s; sm2[t] = m;
    __syncthreads();
    for (int k = 128; k > 0; k >>= 1) {
        if (t < k) { ss[t] += ss[t + k]; sm2[t] = fmaxf(sm2[t], sm2[t + k]); }
        __syncthreads();
    }
    if (t == 0) { g_avg[nc] = ss[0] * (1.f / HWSZ); g_mx[nc] = sm2[0]; }
}

__global__ void gate_k(const float* __restrict__ W1, const float* __restrict__ W2)
{
    __shared__ float h1[NB][2][16];
    int t = threadIdx.x;
    {
        int n = t >> 5, rem = t & 31, path = rem >> 4, r = rem & 15;
        const float* z = (path == 0 ? g_avg : g_mx) + n * CCH;
        float s = 0.f;
        for (int c = 0; c < CCH; c++) s += W1[r * CCH + c] * z[c];
        h1[n][path][r] = fmaxf(s, 0.f);
    }
    __syncthreads();
    int c = t;
    for (int n = 0; n < NB; n++) {
        float g = 0.f;
        for (int r = 0; r < 16; r++)
            g += W2[c * 16 + r] * (h1[n][0][r] + h1[n][1][r]);
        g_gate[n * CCH + c] = 1.f / (1.f + __expf(-g));
    }
}

__global__ void final_k(const float* __restrict__ x,
                        const float* __restrict__ gama,
                        float* __restrict__ o)
{
    size_t idx = (size_t)blockIdx.x * blockDim.x + threadIdx.x;
    float g = gama[0];
    float4 ov = ((const float4*)o)[idx];
    float4 xv = ((const float4*)x)[idx];
    float gt = g * g_gate[idx >> 12];
    float4 r;
    r.x = gt * ov.x + xv.x;
    r.y = gt * ov.y + xv.y;
    r.z = gt * ov.z + xv.z;
    r.w = gt * ov.w + xv.w;
    ((float4*)o)[idx] = r;
}

// ---------------------------------------------------------------------------
extern "C" void kernel_launch(void* const* d_in, const int* in_sizes, int n_in,
                              void* d_out, int out_size)
{
    const float* x    = (const float*)d_in[0];
    const float* Wq   = (const float*)d_in[1];
    const float* Wk   = (const float*)d_in[2];
    const float* Wv   = (const float*)d_in[3];
    const float* W1   = (const float*)d_in[4];
    const float* W2   = (const float*)d_in[5];
    const float* gama = (const float*)d_in[6];
    float* out = (float*)d_out;

    const int PROJ_SMEM = (128 * PA + 32 * PB + 128 * PC) * 2;  // 53,760 B
    const int ATTN_SMEM = 103936;
    cudaFuncSetAttribute(proj_mma, cudaFuncAttributeMaxDynamicSharedMemorySize, PROJ_SMEM);
    cudaFuncSetAttribute(attn_mma, cudaFuncAttributeMaxDynamicSharedMemorySize, ATTN_SMEM);

    convert_x<<<(NB * CCH * HWSZ) / 1024, 256>>>(x);
    convert_w<<<384, 256>>>(Wq, Wk, Wv);

    proj_mma<<<dim3(128, 3, NB), 256, PROJ_SMEM>>>();

    attn_mma<<<NB * HH, 256, ATTN_SMEM>>>(out);

    reduce_nc<<<NB * CCH, 256>>>(out);
    gate_k<<<1, 256>>>(W1, W2);
    final_k<<<(NB * CCH * HWSZ) / 1024, 256>>>(x, gama, out);
}

// round 4
// speedup vs baseline: 3.7700x; 1.0461x over previous
#include <cuda_runtime.h>
#include <cuda_bf16.h>
#include <math.h>

#define NB   8
#define CCH  256
#define HH   128
#define WW   128
#define HWSZ 16384
#define QKD  64

typedef unsigned int u32;
typedef __nv_bfloat16 bf16;

// ---------------- scratch ----------------
__device__ __align__(16) bf16 g_Wb[384 * CCH];          // [Wq;Wk;Wv] bf16
__device__ float g_psum[(size_t)NB * CCH * HH];         // per-(n,c,h) sum
__device__ float g_pmax[(size_t)NB * CCH * HH];         // per-(n,c,h) max
__device__ float g_avg[NB * CCH];
__device__ float g_mx [NB * CCH];
__device__ float g_gate[NB * CCH];

// ---------------- helpers ----------------
__device__ __forceinline__ u32 smem_u32(const void* p) {
    u32 a;
    asm("{.reg .u64 t; cvta.to.shared.u64 t, %1; cvt.u32.u64 %0, t;}"
        : "=r"(a) : "l"(p));
    return a;
}
__device__ __forceinline__ void ldsm4(u32* r, u32 a) {
    asm volatile("ldmatrix.sync.aligned.m8n8.x4.shared.b16 {%0,%1,%2,%3},[%4];"
        : "=r"(r[0]), "=r"(r[1]), "=r"(r[2]), "=r"(r[3]) : "r"(a));
}
__device__ __forceinline__ void ldsm4t(u32* r, u32 a) {
    asm volatile("ldmatrix.sync.aligned.m8n8.x4.trans.shared.b16 {%0,%1,%2,%3},[%4];"
        : "=r"(r[0]), "=r"(r[1]), "=r"(r[2]), "=r"(r[3]) : "r"(a));
}
__device__ __forceinline__ void mma_bf(float* d, const u32* a, const u32* b) {
    asm volatile(
        "mma.sync.aligned.m16n8k16.row.col.f32.bf16.bf16.f32 "
        "{%0,%1,%2,%3},{%4,%5,%6,%7},{%8,%9},{%0,%1,%2,%3};"
        : "+f"(d[0]), "+f"(d[1]), "+f"(d[2]), "+f"(d[3])
        : "r"(a[0]), "r"(a[1]), "r"(a[2]), "r"(a[3]), "r"(b[0]), "r"(b[1]));
}
__device__ __forceinline__ u32 packbf(float lo, float hi) {
    u32 r; asm("cvt.rn.bf16x2.f32 %0,%1,%2;" : "=r"(r) : "f"(hi), "f"(lo));
    return r;
}

// ---------------------------------------------------------------------------
__global__ void convert_w(const float* __restrict__ Wq,
                          const float* __restrict__ Wk,
                          const float* __restrict__ Wv)
{
    int i = blockIdx.x * 256 + threadIdx.x;
    float v;
    if (i < 64 * 256)       v = Wq[i];
    else if (i < 128 * 256) v = Wk[i - 64 * 256];
    else                    v = Wv[i - 128 * 256];
    g_Wb[i] = __float2bfloat16(v);
}

// ---------------------------------------------------------------------------
// smem layout (bytes):
//  A: [0, 69632)       xt bf16 [256][136]   / later S fp32 [128][130]
//  B: [69632, 104448)  qk bf16 [128][136]   / later att bf16 [128][136]
//  C: [104448, 174080) v  bf16 [256][136]
//  W: [174080, 184320) W stage bf16 [128][40] / later psum/pmax [128][4] each
//  I: [184320, 184832) inv fp32 [128]
// ---------------------------------------------------------------------------
#define XT_PITCH 136
#define S_PITCH  130
#define QP       136
#define SMEM_TOTAL 184832

// in-smem GEMM: dst[128][QP] (bf16) = W[128][256] @ xt[256][128]
__device__ __forceinline__ void gemm_wx(const bf16* __restrict__ Wbase,
                                        bf16* wb, const bf16* xt, bf16* dst,
                                        int t, int l, int m0, int n0)
{
    float acc[4][4][4];
#pragma unroll
    for (int a = 0; a < 4; a++)
#pragma unroll
        for (int b = 0; b < 4; b++)
#pragma unroll
            for (int c = 0; c < 4; c++) acc[a][b][c] = 0.f;

    for (int kk = 0; kk < 256; kk += 32) {
        __syncthreads();                       // protect wb reuse
        {
            int r = t >> 1, ko = (t & 1) * 16;
            *(uint4*)(wb + r * 40 + ko)     = *(const uint4*)(Wbase + (size_t)r * 256 + kk + ko);
            *(uint4*)(wb + r * 40 + ko + 8) = *(const uint4*)(Wbase + (size_t)r * 256 + kk + ko + 8);
        }
        __syncthreads();

#pragma unroll
        for (int ks = 0; ks < 2; ks++) {
            int k0 = ks * 16;
            u32 a[4][4], b[4][2];
            int ar  = ((l >> 3) & 1) * 8 + (l & 7);
            int acl = k0 + (l >> 4) * 8;
#pragma unroll
            for (int mf = 0; mf < 4; mf++)
                ldsm4(a[mf], smem_u32(wb + (m0 + mf * 16 + ar) * 40 + acl));
            int br  = kk + k0 + ((l >> 3) & 1) * 8 + (l & 7);
            int bcl = (l >> 4) * 8;
#pragma unroll
            for (int bi = 0; bi < 2; bi++) {
                u32 r4[4];
                ldsm4t(r4, smem_u32(xt + br * XT_PITCH + n0 + bi * 16 + bcl));
                b[bi * 2][0] = r4[0]; b[bi * 2][1] = r4[1];
                b[bi * 2 + 1][0] = r4[2]; b[bi * 2 + 1][1] = r4[3];
            }
#pragma unroll
            for (int mf = 0; mf < 4; mf++)
#pragma unroll
                for (int nf = 0; nf < 4; nf++)
                    mma_bf(acc[mf][nf], a[mf], b[nf]);
        }
    }

    int g = l >> 2, tq = l & 3;
#pragma unroll
    for (int mf = 0; mf < 4; mf++)
#pragma unroll
        for (int nf = 0; nf < 4; nf++) {
            int col = n0 + nf * 8 + tq * 2;
            *(u32*)(dst + (m0 + mf * 16 + g) * QP + col)     = packbf(acc[mf][nf][0], acc[mf][nf][1]);
            *(u32*)(dst + (m0 + mf * 16 + g + 8) * QP + col) = packbf(acc[mf][nf][2], acc[mf][nf][3]);
        }
}

__global__ __launch_bounds__(256, 1) void fused_attn(const float* __restrict__ x,
                                                     float* __restrict__ out)
{
    extern __shared__ char smc[];
    bf16*  xt    = (bf16*)smc;
    float* S_s   = (float*)smc;
    bf16*  qk_s  = (bf16*)(smc + 69632);
    bf16*  att_s = qk_s;
    bf16*  v_s   = (bf16*)(smc + 104448);
    bf16*  wb    = (bf16*)(smc + 174080);
    float* psum  = (float*)(smc + 174080);   // overlays wb (dead after GEMMs)
    float* pmax  = psum + 512;
    float* inv_s = (float*)(smc + 184320);

    int nh = blockIdx.x, n = nh >> 7, h = nh & 127;
    int t = threadIdx.x, l = t & 31, w = t >> 5;
    int m0 = (w & 1) * 64, n0 = (w >> 1) * 32;

    // ---- load x tile (fp32 -> bf16 in-register) ----
    for (int e = t; e < 8192; e += 256) {
        int c = e >> 5, i4 = (e & 31) << 2;
        float4 v4 = *(const float4*)(x + ((size_t)(n * CCH + c) * HH + h) * WW + i4);
        uint2 o;
        o.x = packbf(v4.x, v4.y);
        o.y = packbf(v4.z, v4.w);
        *(uint2*)(xt + c * XT_PITCH + i4) = o;
    }
    __syncthreads();

    // ---- projections: qk (q rows 0-63, k rows 64-127) and v (256 rows) ----
    gemm_wx(g_Wb,             wb, xt, qk_s,           t, l, m0, n0);
    gemm_wx(g_Wb + 128 * 256, wb, xt, v_s,            t, l, m0, n0);
    gemm_wx(g_Wb + 256 * 256, wb, xt, v_s + 128 * QP, t, l, m0, n0);
    __syncthreads();   // all xt reads done; qk/v visible

    // ---- logits: S[i][j] = sum_d q[d][i] k[d][j]  (overwrites xt region) ----
    {
        float acc[4][4][4];
#pragma unroll
        for (int a = 0; a < 4; a++)
#pragma unroll
            for (int b = 0; b < 4; b++)
#pragma unroll
                for (int c = 0; c < 4; c++) acc[a][b][c] = 0.f;

        const bf16* k_s = qk_s + 64 * QP;
#pragma unroll
        for (int ks = 0; ks < 4; ks++) {
            int k0 = ks * 16;
            u32 a[4][4], b[4][2];
            int ar  = k0 + ((l >> 4) << 3) + (l & 7);
            int acl = ((l >> 3) & 1) * 8;
#pragma unroll
            for (int mf = 0; mf < 4; mf++)
                ldsm4t(a[mf], smem_u32(qk_s + ar * QP + m0 + mf * 16 + acl));
            int br  = k0 + ((l >> 3) & 1) * 8 + (l & 7);
            int bcl = (l >> 4) * 8;
#pragma unroll
            for (int bi = 0; bi < 2; bi++) {
                u32 r4[4];
                ldsm4t(r4, smem_u32(k_s + br * QP + n0 + bi * 16 + bcl));
                b[bi * 2][0] = r4[0]; b[bi * 2][1] = r4[1];
                b[bi * 2 + 1][0] = r4[2]; b[bi * 2 + 1][1] = r4[3];
            }
#pragma unroll
            for (int mf = 0; mf < 4; mf++)
#pragma unroll
                for (int nf = 0; nf < 4; nf++)
                    mma_bf(acc[mf][nf], a[mf], b[nf]);
        }
        int g = l >> 2, tq = l & 3;
#pragma unroll
        for (int mf = 0; mf < 4; mf++)
#pragma unroll
            for (int nf = 0; nf < 4; nf++) {
                int i = m0 + mf * 16 + g, j = n0 + nf * 8 + tq * 2;
                *(float2*)(S_s + i * S_PITCH + j)       = make_float2(acc[mf][nf][0], acc[mf][nf][1]);
                *(float2*)(S_s + (i + 8) * S_PITCH + j) = make_float2(acc[mf][nf][2], acc[mf][nf][3]);
            }
    }
    __syncthreads();

    // ---- softmax over j per row i; exp -> att_s bf16 (overwrites qk) ----
    {
        int i = t >> 1, hf = t & 1;
        const float* Sr = S_s + i * S_PITCH;
        float m = -1e30f;
#pragma unroll 8
        for (int jj = 0; jj < 64; jj++) m = fmaxf(m, Sr[2 * jj + hf]);
        m = fmaxf(m, __shfl_xor_sync(0xffffffffu, m, 1));
        float s = 0.f;
        bf16* ar = att_s + i * QP;
#pragma unroll 8
        for (int jj = 0; jj < 64; jj++) {
            int j = 2 * jj + hf;
            float e = __expf(Sr[j] - m);
            s += e;
            ar[j] = __float2bfloat16(e);
        }
        s += __shfl_xor_sync(0xffffffffu, s, 1);
        if (hf == 0) inv_s[i] = 1.f / s;
    }
    __syncthreads();

    // ---- att . V : out[c][i], 2 chunks of 128 channels (v already in smem) ----
    for (int cc = 0; cc < 2; cc++) {
        const bf16* vc = v_s + (size_t)cc * 128 * QP;

        float acc[4][4][4];
#pragma unroll
        for (int a = 0; a < 4; a++)
#pragma unroll
            for (int b = 0; b < 4; b++)
#pragma unroll
                for (int c = 0; c < 4; c++) acc[a][b][c] = 0.f;

#pragma unroll
        for (int ks = 0; ks < 8; ks++) {
            int k0 = ks * 16;
            u32 a[4][4], b[4][2];
            int ar  = ((l >> 3) & 1) * 8 + (l & 7);
            int acl = k0 + (l >> 4) * 8;
#pragma unroll
            for (int mf = 0; mf < 4; mf++)
                ldsm4(a[mf], smem_u32(vc + (m0 + mf * 16 + ar) * QP + acl));
            int brr = (l >> 4) * 8 + (l & 7);
            int bcl = k0 + ((l >> 3) & 1) * 8;
#pragma unroll
            for (int bi = 0; bi < 2; bi++) {
                u32 r4[4];
                ldsm4(r4, smem_u32(att_s + (n0 + bi * 16 + brr) * QP + bcl));
                b[bi * 2][0] = r4[0]; b[bi * 2][1] = r4[1];
                b[bi * 2 + 1][0] = r4[2]; b[bi * 2 + 1][1] = r4[3];
            }
#pragma unroll
            for (int mf = 0; mf < 4; mf++)
#pragma unroll
                for (int nf = 0; nf < 4; nf++)
                    mma_bf(acc[mf][nf], a[mf], b[nf]);
        }

        // epilogue: scale by 1/sum, write out, accumulate per-c partials
        int g = l >> 2, tq = l & 3;
        int wg = w >> 1;
#pragma unroll
        for (int mf = 0; mf < 4; mf++) {
            float rs0 = 0.f, rs1 = 0.f, rm0 = -1e30f, rm1 = -1e30f;
#pragma unroll
            for (int nf = 0; nf < 4; nf++) {
                int i = n0 + nf * 8 + tq * 2;
                float2 iv = *(float2*)(inv_s + i);
                int c = m0 + mf * 16 + g;
                float o0 = acc[mf][nf][0] * iv.x;
                float o1 = acc[mf][nf][1] * iv.y;
                float o2 = acc[mf][nf][2] * iv.x;
                float o3 = acc[mf][nf][3] * iv.y;
                size_t b0 = (((size_t)n * CCH + cc * 128 + c) * HH + h) * (size_t)WW + i;
                size_t b1 = (((size_t)n * CCH + cc * 128 + c + 8) * HH + h) * (size_t)WW + i;
                *(float2*)(out + b0) = make_float2(o0, o1);
                *(float2*)(out + b1) = make_float2(o2, o3);
                rs0 += o0 + o1; rm0 = fmaxf(rm0, fmaxf(o0, o1));
                rs1 += o2 + o3; rm1 = fmaxf(rm1, fmaxf(o2, o3));
            }
            // reduce across the 4 lanes (tq) sharing each row
#pragma unroll
            for (int off = 1; off < 4; off <<= 1) {
                rs0 += __shfl_xor_sync(0xffffffffu, rs0, off);
                rs1 += __shfl_xor_sync(0xffffffffu, rs1, off);
                rm0 = fmaxf(rm0, __shfl_xor_sync(0xffffffffu, rm0, off));
                rm1 = fmaxf(rm1, __shfl_xor_sync(0xffffffffu, rm1, off));
            }
            if (tq == 0) {
                int c128 = m0 + mf * 16 + g;
                psum[c128 * 4 + wg]       = rs0;
                psum[(c128 + 8) * 4 + wg] = rs1;
                pmax[c128 * 4 + wg]       = rm0;
                pmax[(c128 + 8) * 4 + wg] = rm1;
            }
        }
        __syncthreads();
        if (t < 128) {
            float s = psum[t * 4] + psum[t * 4 + 1] + psum[t * 4 + 2] + psum[t * 4 + 3];
            float m = fmaxf(fmaxf(pmax[t * 4], pmax[t * 4 + 1]),
                            fmaxf(pmax[t * 4 + 2], pmax[t * 4 + 3]));
            size_t nc = (size_t)n * CCH + cc * 128 + t;
            g_psum[nc * HH + h] = s;
            g_pmax[nc * HH + h] = m;
        }
        __syncthreads();
    }
}

// ---------------------------------------------------------------------------
__global__ void reduce2()
{
    __shared__ float ss[4], sm[4];
    int nc = blockIdx.x, t = threadIdx.x;
    float s = g_psum[(size_t)nc * HH + t];
    float m = g_pmax[(size_t)nc * HH + t];
#pragma unroll
    for (int o = 16; o > 0; o >>= 1) {
        s += __shfl_xor_sync(0xffffffffu, s, o);
        m = fmaxf(m, __shfl_xor_sync(0xffffffffu, m, o));
    }
    if ((t & 31) == 0) { ss[t >> 5] = s; sm[t >> 5] = m; }
    __syncthreads();
    if (t == 0) {
        float S = ss[0] + ss[1] + ss[2] + ss[3];
        float M = fmaxf(fmaxf(sm[0], sm[1]), fmaxf(sm[2], sm[3]));
        g_avg[nc] = S * (1.f / HWSZ);
        g_mx[nc]  = M;
    }
}

__global__ void gate_k(const float* __restrict__ W1, const float* __restrict__ W2)
{
    __shared__ float h1[NB][2][16];
    int t = threadIdx.x;
    {
        int n = t >> 5, rem = t & 31, path = rem >> 4, r = rem & 15;
        const float* z = (path == 0 ? g_avg : g_mx) + n * CCH;
        float s = 0.f;
        for (int c = 0; c < CCH; c++) s += W1[r * CCH + c] * z[c];
        h1[n][path][r] = fmaxf(s, 0.f);
    }
    __syncthreads();
    int c = t;
    for (int n = 0; n < NB; n++) {
        float g = 0.f;
        for (int r = 0; r < 16; r++)
            g += W2[c * 16 + r] * (h1[n][0][r] + h1[n][1][r]);
        g_gate[n * CCH + c] = 1.f / (1.f + __expf(-g));
    }
}

__global__ void final_k(const float* __restrict__ x,
                        const float* __restrict__ gama,
                        float* __restrict__ o)
{
    size_t idx = (size_t)blockIdx.x * blockDim.x + threadIdx.x;
    float g = gama[0];
    float4 ov = ((const float4*)o)[idx];
    float4 xv = ((const float4*)x)[idx];
    float gt = g * g_gate[idx >> 12];
    float4 r;
    r.x = gt * ov.x + xv.x;
    r.y = gt * ov.y + xv.y;
    r.z = gt * ov.z + xv.z;
    r.w = gt * ov.w + xv.w;
    ((float4*)o)[idx] = r;
}

// ---------------------------------------------------------------------------
extern "C" void kernel_launch(void* const* d_in, const int* in_sizes, int n_in,
                              void* d_out, int out_size)
{
    const float* x    = (const float*)d_in[0];
    const float* Wq   = (const float*)d_in[1];
    const float* Wk   = (const float*)d_in[2];
    const float* Wv   = (const float*)d_in[3];
    const float* W1   = (const float*)d_in[4];
    const float* W2   = (const float*)d_in[5];
    const float* gama = (const float*)d_in[6];
    float* out = (float*)d_out;

    cudaFuncSetAttribute(fused_attn, cudaFuncAttributeMaxDynamicSharedMemorySize, SMEM_TOTAL);

    convert_w<<<384, 256>>>(Wq, Wk, Wv);
    fused_attn<<<NB * HH, 256, SMEM_TOTAL>>>(x, out);
    reduce2<<<NB * CCH, 128>>>();
    gate_k<<<1, 256>>>(W1, W2);
    final_k<<<(NB * CCH * HWSZ) / 1024, 256>>>(x, gama, out);
}